// round 10
// baseline (speedup 1.0000x reference)
#include <cuda_runtime.h>
#include <cuda_bf16.h>
#include <math.h>
#include <stdint.h>

// NCE loss: scores(16384x104) = inp(16384x512) @ noise_emb^T via HMMA bf16.
// Grid=256 = 128 token-blocks x 2 column-groups; 256 thr; 2 CTAs/SM.
// grp0: n-tiles 0-6 (+64 target dots), grp1: n-tiles 7-12 (+64 target dots).
// A staged f32 via cp.async 3-chunk ring (2 ksteps/chunk); B fragments
// double-buffered in registers (ldmatrix of ks+1 overlaps MMAs of ks).

#define E      512
#define NRR    100
#define TPB    256
#define GRID1  256
#define NTOK   16384

#define AROW   144                  // 32 f32 (128B) + 16B pad
#define ACH    18432                // 128 * 144
#define SM_B     0                  // up to 56 rows * 1024B
#define SM_SC    57344              // 56 floats
#define SM_RED   57600              // 8 floats
#define SM_FLAG  57632
#define SM_AR    57664              // 3 * 18432
#define SM_TOTAL 112960

__device__ float        g_partials[GRID1];
__device__ unsigned int g_counter;

struct __align__(16) u64x2 { unsigned long long x, y; };

__device__ __forceinline__ unsigned long long fma2(unsigned long long a,
                                                   unsigned long long b,
                                                   unsigned long long c) {
    unsigned long long d;
    asm("fma.rn.f32x2 %0, %1, %2, %3;" : "=l"(d) : "l"(a), "l"(b), "l"(c));
    return d;
}
__device__ __forceinline__ float pairsum(unsigned long long u) {
    float lo, hi;
    asm("mov.b64 {%0, %1}, %2;" : "=f"(lo), "=f"(hi) : "l"(u));
    return lo + hi;
}
__device__ __forceinline__ float softplus_fast(float x) {
    return fmaxf(x, 0.0f) + __logf(1.0f + __expf(-fabsf(x)));
}
__device__ __forceinline__ uint32_t smem_u32(const void* p) {
    uint32_t a;
    asm("{ .reg .u64 t; cvta.to.shared.u64 t, %1; cvt.u32.u64 %0, t; }"
        : "=r"(a) : "l"(p));
    return a;
}
__device__ __forceinline__ uint32_t bf2(float lo, float hi) {
    uint32_t r;
    asm("cvt.rn.bf16x2.f32 %0, %1, %2;" : "=r"(r) : "f"(hi), "f"(lo));
    return r;
}
__device__ __forceinline__ void mma16816(float* d,
        uint32_t a0, uint32_t a1, uint32_t a2, uint32_t a3,
        uint32_t b0, uint32_t b1) {
    asm volatile("mma.sync.aligned.m16n8k16.row.col.f32.bf16.bf16.f32 "
        "{%0,%1,%2,%3}, {%4,%5,%6,%7}, {%8,%9}, {%0,%1,%2,%3};"
        : "+f"(d[0]), "+f"(d[1]), "+f"(d[2]), "+f"(d[3])
        : "r"(a0), "r"(a1), "r"(a2), "r"(a3), "r"(b0), "r"(b1));
}

__global__ void __launch_bounds__(TPB, 2)
nce_hmma(const float* __restrict__ inp,
         const float* __restrict__ emb,
         const float* __restrict__ bias,
         const float* __restrict__ logn,
         const int*   __restrict__ target,
         const int*   __restrict__ noise_idx,
         float csub, float* __restrict__ out)
{
    extern __shared__ char smem[];
    const uint32_t sb = smem_u32(smem);
    const int tid = threadIdx.x, warp = tid >> 5, lane = tid & 31;
    const int gid = lane >> 2, ctg = lane & 3;
    const int grp = blockIdx.x & 1;          // 0: tiles 0-6, 1: tiles 7-12
    const int tokBase = (blockIdx.x >> 1) * 128;
    const int NTILE = grp ? 6 : 7;
    const int NROWS = NTILE * 8;             // 56 or 48 local B rows
    const int colBase = grp * 56;
    float* sC    = (float*)(smem + SM_SC);
    float* sRed  = (float*)(smem + SM_RED);
    int*   sFlag = (int*)(smem + SM_FLAG);

    // ---- prologue: commit A chunks 0,1 via cp.async (ring of 3)
    auto stageA = [&](int c) {
        const uint32_t dbase = sb + (uint32_t)(SM_AR + (c % 3) * ACH);
        #pragma unroll
        for (int i = 0; i < 4; ++i) {
            int idx = tid + i * TPB;         // 1024 16B units
            int row = idx >> 3, u = idx & 7; // 8 x 16B per row (32 f32)
            const char* src = (const char*)(inp + (size_t)(tokBase + row) * E
                                            + c * 32) + u * 16;
            uint32_t sa = dbase + (uint32_t)(row * AROW + u * 16);
            asm volatile("cp.async.cg.shared.global [%0], [%1], 16;"
                         :: "r"(sa), "l"(src));
        }
        asm volatile("cp.async.commit_group;");
    };
    stageA(0);
    stageA(1);

    // ---- stage B: NROWS x 512 bf16, 16B chunks XOR-swizzled per local row
    for (int i = tid; i < NROWS * 64; i += TPB) {
        int n = i >> 6, c = i & 63;
        int col = colBase + n;
        uint4 pk = make_uint4(0u, 0u, 0u, 0u);
        if (col < NRR) {
            int nid = noise_idx[col];
            const float4* r = (const float4*)(emb + (size_t)nid * E) + (c << 1);
            float4 v0 = r[0], v1 = r[1];
            pk.x = bf2(v0.x, v0.y); pk.y = bf2(v0.z, v0.w);
            pk.z = bf2(v1.x, v1.y); pk.w = bf2(v1.z, v1.w);
        }
        *(uint4*)(smem + SM_B + n * 1024 + ((c ^ (n & 7)) << 4)) = pk;
    }
    if (tid < NROWS) {
        int col = colBase + tid;
        float cv = -INFINITY;               // pad cols 100-103 -> softplus 0
        if (col < NRR) {
            int nid = noise_idx[col];
            cv = bias[nid] - logn[nid] - csub;
        }
        sC[tid] = cv;
    }
    __syncthreads();

    float myLoss = 0.0f;

    // ---- target dots: this CTA handles 64 tokens (8/warp), fp32 exact.
    // Runs while the co-resident CTA computes; A chunks keep landing.
    #pragma unroll 1
    for (int i = 0; i < 8; i += 2) {
        int t0 = tokBase + grp * 64 + warp * 8 + i;
        int tg0 = target[t0], tg1 = target[t0 + 1];
        const u64x2* i0 = (const u64x2*)(inp + (size_t)t0 * E);
        const u64x2* i1 = (const u64x2*)(inp + (size_t)(t0 + 1) * E);
        const u64x2* e0 = (const u64x2*)(emb + (size_t)tg0 * E);
        const u64x2* e1 = (const u64x2*)(emb + (size_t)tg1 * E);
        unsigned long long A0 = 0ull, A1 = 0ull;
        #pragma unroll
        for (int q = 0; q < 4; ++q) {
            u64x2 a = i0[lane + q * 32], b = e0[lane + q * 32];
            u64x2 c = i1[lane + q * 32], d = e1[lane + q * 32];
            A0 = fma2(a.x, b.x, A0); A0 = fma2(a.y, b.y, A0);
            A1 = fma2(c.x, d.x, A1); A1 = fma2(c.y, d.y, A1);
        }
        float s0 = pairsum(A0), s1 = pairsum(A1);
        #pragma unroll
        for (int d = 16; d >= 1; d >>= 1) {
            s0 += __shfl_xor_sync(0xffffffffu, s0, d);
            s1 += __shfl_xor_sync(0xffffffffu, s1, d);
        }
        if (lane == 0) {
            myLoss += softplus_fast(-(s0 + bias[tg0] - logn[tg0] - csub));
            myLoss += softplus_fast(-(s1 + bias[tg1] - logn[tg1] - csub));
        }
    }

    // ---- GEMM: 16 token rows x NTILE n-tiles, K=512, 16 chunks of 2 ksteps
    float acc[7][4];
    #pragma unroll
    for (int t = 0; t < 7; ++t)
        #pragma unroll
        for (int r = 0; r < 4; ++r) acc[t][r] = 0.0f;

    // ldmatrix slots: 3 x4 (local tiles 0-5) + 1 x2 (local tile 6, grp0 only)
    int nb[4], m7[4];
    #pragma unroll
    for (int p = 0; p < 3; ++p) {
        int n = (2 * p + (lane >> 4)) * 8 + (lane & 7);
        nb[p] = n * 1024; m7[p] = n & 7;
    }
    { int n = 48 + (lane & 7); nb[3] = n * 1024; m7[3] = n & 7; }
    const int khB = (lane >> 3) & 1;

    uint32_t fb[2][14];                      // double-buffered B fragments
    auto loadB = [&](int ks, int b) {
        const int cb = ks * 2 + khB;
        #pragma unroll
        for (int p = 0; p < 3; ++p) {
            uint32_t addr = sb + (uint32_t)(nb[p] + ((cb ^ m7[p]) << 4));
            asm volatile("ldmatrix.sync.aligned.m8n8.x4.shared.b16 "
                         "{%0,%1,%2,%3}, [%4];"
                         : "=r"(fb[b][4*p]), "=r"(fb[b][4*p+1]),
                           "=r"(fb[b][4*p+2]), "=r"(fb[b][4*p+3]) : "r"(addr));
        }
        if (grp == 0) {
            uint32_t addr = sb + (uint32_t)(nb[3] + ((cb ^ m7[3]) << 4));
            asm volatile("ldmatrix.sync.aligned.m8n8.x2.shared.b16 "
                         "{%0,%1}, [%2];"
                         : "=r"(fb[b][12]), "=r"(fb[b][13]) : "r"(addr));
        }
    };
    loadB(0, 0);

    const int arow0 = (warp * 16 + gid) * AROW + ctg * 8;

    #pragma unroll 1
    for (int c = 0; c < 16; ++c) {
        if (c < 15) asm volatile("cp.async.wait_group 1;" ::: "memory");
        else        asm volatile("cp.async.wait_group 0;" ::: "memory");
        __syncthreads();
        if (c + 2 < 16) stageA(c + 2);       // buf (c+2)%3 freed at iter c-1

        const char* Ab = smem + SM_AR + (c % 3) * ACH;

        #pragma unroll
        for (int kl = 0; kl < 2; ++kl) {
            const int ks = c * 2 + kl;
            const int cur = ks & 1;
            // A fragment from ring (f32 -> bf16)
            const char* a0p = Ab + arow0 + kl * 64;
            const char* a1p = a0p + 8 * AROW;
            float2 g0 = *(const float2*)(a0p);
            float2 g2 = *(const float2*)(a0p + 32);
            float2 g1 = *(const float2*)(a1p);
            float2 g3 = *(const float2*)(a1p + 32);
            // B fragments for next kstep overlap this kstep's MMAs (B static)
            if (ks < 31) loadB(ks + 1, cur ^ 1);
            uint32_t a0 = bf2(g0.x, g0.y), a1 = bf2(g1.x, g1.y);
            uint32_t a2 = bf2(g2.x, g2.y), a3 = bf2(g3.x, g3.y);
            #pragma unroll
            for (int p = 0; p < 3; ++p) {
                mma16816(acc[2*p],   a0, a1, a2, a3, fb[cur][4*p],   fb[cur][4*p+1]);
                mma16816(acc[2*p+1], a0, a1, a2, a3, fb[cur][4*p+2], fb[cur][4*p+3]);
            }
            if (grp == 0)
                mma16816(acc[6], a0, a1, a2, a3, fb[cur][12], fb[cur][13]);
        }
    }

    // ---- epilogue: softplus over this CTA's 128 x (48|56) scores
    #pragma unroll
    for (int t = 0; t < 7; ++t) {
        if (t >= NTILE) break;
        float c0 = sC[t * 8 + ctg * 2];
        float c1 = sC[t * 8 + ctg * 2 + 1];
        myLoss += softplus_fast(acc[t][0] + c0);
        myLoss += softplus_fast(acc[t][1] + c1);
        myLoss += softplus_fast(acc[t][2] + c0);
        myLoss += softplus_fast(acc[t][3] + c1);
    }

    // ---- block reduce
    #pragma unroll
    for (int d = 16; d >= 1; d >>= 1)
        myLoss += __shfl_xor_sync(0xffffffffu, myLoss, d);
    if (lane == 0) sRed[warp] = myLoss;
    __syncthreads();

    // ---- cross-block: last block reduces (single kernel)
    if (tid == 0) {
        float s = 0.f;
        #pragma unroll
        for (int w = 0; w < 8; ++w) s += sRed[w];
        g_partials[blockIdx.x] = s;
        __threadfence();
        unsigned n = atomicAdd(&g_counter, 1u);
        sFlag[0] = (n == GRID1 - 1) ? 1 : 0;
    }
    __syncthreads();
    if (sFlag[0]) {
        float v = g_partials[tid];           // GRID1 == TPB
        #pragma unroll
        for (int d = 16; d >= 1; d >>= 1)
            v += __shfl_xor_sync(0xffffffffu, v, d);
        if (lane == 0) sRed[warp] = v;
        __syncthreads();
        if (tid == 0) {
            float s = 0.f;
            #pragma unroll
            for (int w = 0; w < 8; ++w) s += sRed[w];
            out[0] = s * (1.0f / (float)NTOK);
            g_counter = 0u;                  // reset for next graph replay
        }
    }
}

extern "C" void kernel_launch(void* const* d_in, const int* in_sizes, int n_in,
                              void* d_out, int out_size) {
    (void)in_sizes; (void)n_in; (void)out_size;
    const float* inp       = (const float*)d_in[0];
    const float* emb       = (const float*)d_in[1];
    const float* bias      = (const float*)d_in[2];
    const float* logn      = (const float*)d_in[3];
    const int*   target    = (const int*)d_in[4];
    const int*   noise_idx = (const int*)d_in[5];

    float csub = logf(50257.0f) + logf(100.0f);   // NORM_TERM + LOG_NR

    cudaFuncSetAttribute(nce_hmma, cudaFuncAttributeMaxDynamicSharedMemorySize, SM_TOTAL);
    nce_hmma<<<GRID1, TPB, SM_TOTAL>>>(inp, emb, bias, logn, target, noise_idx,
                                       csub, (float*)d_out);
}

// round 13
// speedup vs baseline: 1.0736x; 1.0736x over previous
#include <cuda_runtime.h>
#include <cuda_bf16.h>
#include <math.h>
#include <stdint.h>

// NCE loss: scores(16384x104) = inp(16384x512) @ noise_emb^T via HMMA bf16.
// Grid=128 CTAs x 256 thr, 128 tokens/CTA, 1 CTA/SM.
// A: cp.async f32 3-chunk ring (inner loop = LDS only). B: smem bf16
// (XOR-swizzled), fragments double-buffered in registers (ldmatrix ks+1
// overlaps MMAs of ks). Target dots: separate phase, 4-wide MLP, fp32.

#define E      512
#define NRR    100
#define NP     104          // 13 * 8
#define NT     13
#define TPB    256
#define GRID1  128
#define NTOK   16384

#define AROW   272          // 64 f32 (256B) + 16B pad
#define ACH    34816        // 128 * 272
#define SM_B     0          // 104 * 1024
#define SM_SC    106496     // 104 floats
#define SM_NID   106912     // 104 ints
#define SM_RED   107328     // 8 floats
#define SM_FLAG  107392
#define SM_AR    107424     // 3 * 34816  (16B aligned)
#define SM_TOTAL 211904

__device__ float        g_partials[GRID1];
__device__ unsigned int g_counter;

struct __align__(16) u64x2 { unsigned long long x, y; };

__device__ __forceinline__ unsigned long long fma2(unsigned long long a,
                                                   unsigned long long b,
                                                   unsigned long long c) {
    unsigned long long d;
    asm("fma.rn.f32x2 %0, %1, %2, %3;" : "=l"(d) : "l"(a), "l"(b), "l"(c));
    return d;
}
__device__ __forceinline__ float pairsum(unsigned long long u) {
    float lo, hi;
    asm("mov.b64 {%0, %1}, %2;" : "=f"(lo), "=f"(hi) : "l"(u));
    return lo + hi;
}
__device__ __forceinline__ float softplus_fast(float x) {
    return fmaxf(x, 0.0f) + __logf(1.0f + __expf(-fabsf(x)));
}
__device__ __forceinline__ uint32_t smem_u32(const void* p) {
    uint32_t a;
    asm("{ .reg .u64 t; cvta.to.shared.u64 t, %1; cvt.u32.u64 %0, t; }"
        : "=r"(a) : "l"(p));
    return a;
}
__device__ __forceinline__ uint32_t bf2(float lo, float hi) {
    uint32_t r;
    asm("cvt.rn.bf16x2.f32 %0, %1, %2;" : "=r"(r) : "f"(hi), "f"(lo));
    return r;
}
__device__ __forceinline__ void mma16816(float* d,
        uint32_t a0, uint32_t a1, uint32_t a2, uint32_t a3,
        uint32_t b0, uint32_t b1) {
    asm volatile("mma.sync.aligned.m16n8k16.row.col.f32.bf16.bf16.f32 "
        "{%0,%1,%2,%3}, {%4,%5,%6,%7}, {%8,%9}, {%0,%1,%2,%3};"
        : "+f"(d[0]), "+f"(d[1]), "+f"(d[2]), "+f"(d[3])
        : "r"(a0), "r"(a1), "r"(a2), "r"(a3), "r"(b0), "r"(b1));
}

__global__ void __launch_bounds__(TPB, 1)
nce_hmma(const float* __restrict__ inp,
         const float* __restrict__ emb,
         const float* __restrict__ bias,
         const float* __restrict__ logn,
         const int*   __restrict__ target,
         const int*   __restrict__ noise_idx,
         float csub, float* __restrict__ out)
{
    extern __shared__ char smem[];
    const uint32_t sb = smem_u32(smem);
    const int tid = threadIdx.x, warp = tid >> 5, lane = tid & 31;
    const int gid = lane >> 2, ctg = lane & 3;
    float* sC    = (float*)(smem + SM_SC);
    int*   sNid  = (int*)(smem + SM_NID);
    float* sRed  = (float*)(smem + SM_RED);
    int*   sFlag = (int*)(smem + SM_FLAG);
    const int tokBase = blockIdx.x * 128;

    // ---- A ring: stage chunk c (128 rows x 64 f32) into buf c%3
    auto stageA = [&](int c) {
        const uint32_t dbase = sb + (uint32_t)(SM_AR + (c % 3) * ACH);
        #pragma unroll
        for (int i = 0; i < 8; ++i) {
            int idx = tid + i * TPB;         // 2048 16B units
            int row = idx >> 4, u = idx & 15;
            const char* src = (const char*)(inp + (size_t)(tokBase + row) * E
                                            + c * 64) + u * 16;
            uint32_t sa = dbase + (uint32_t)(row * AROW + u * 16);
            asm volatile("cp.async.cg.shared.global [%0], [%1], 16;"
                         :: "r"(sa), "l"(src));
        }
        asm volatile("cp.async.commit_group;");
    };
    stageA(0);
    stageA(1);

    // ---- column ids + constants to smem first (kills gather dependency)
    if (tid < NP) {
        int nid = (tid < NRR) ? noise_idx[tid] : 0;
        sNid[tid] = nid;
        sC[tid] = (tid < NRR) ? (bias[nid] - logn[nid] - csub) : -INFINITY;
    }
    __syncthreads();

    // ---- stage B: 104 x 512 bf16, 16B chunks XOR-swizzled (unrolled x4)
    #pragma unroll 4
    for (int i = 0; i < 26; ++i) {
        int idx = tid + i * TPB;             // 6656 slots
        int n = idx >> 6, c = idx & 63;
        uint4 pk = make_uint4(0u, 0u, 0u, 0u);
        if (n < NRR) {
            const float4* r = (const float4*)(emb + (size_t)sNid[n] * E) + (c << 1);
            float4 v0 = r[0], v1 = r[1];
            pk.x = bf2(v0.x, v0.y); pk.y = bf2(v0.z, v0.w);
            pk.z = bf2(v1.x, v1.y); pk.w = bf2(v1.z, v1.w);
        }
        *(uint4*)(smem + SM_B + n * 1024 + ((c ^ (n & 7)) << 4)) = pk;
    }

    float myLoss = 0.0f;

    // ---- target dots: 16 tokens/warp, 4 in flight
    #pragma unroll 1
    for (int i = 0; i < 16; i += 4) {
        int tb = tokBase + warp * 16 + i;
        int tg[4];
        #pragma unroll
        for (int j = 0; j < 4; ++j) tg[j] = target[tb + j];
        unsigned long long A[4] = {0ull, 0ull, 0ull, 0ull};
        #pragma unroll
        for (int q = 0; q < 4; ++q) {
            u64x2 av[4], bv[4];
            #pragma unroll
            for (int j = 0; j < 4; ++j) {
                av[j] = ((const u64x2*)(inp + (size_t)(tb + j) * E))[lane + q * 32];
                bv[j] = ((const u64x2*)(emb + (size_t)tg[j] * E))[lane + q * 32];
            }
            #pragma unroll
            for (int j = 0; j < 4; ++j) {
                A[j] = fma2(av[j].x, bv[j].x, A[j]);
                A[j] = fma2(av[j].y, bv[j].y, A[j]);
            }
        }
        #pragma unroll
        for (int j = 0; j < 4; ++j) {
            float s = pairsum(A[j]);
            #pragma unroll
            for (int d = 16; d >= 1; d >>= 1)
                s += __shfl_xor_sync(0xffffffffu, s, d);
            if (lane == 0)
                myLoss += softplus_fast(-(s + bias[tg[j]] - logn[tg[j]] - csub));
        }
    }

    // ---- GEMM: 16 rows x 13 tiles, K=512 = 8 chunks x 4 ksteps
    float acc[NT][4];
    #pragma unroll
    for (int t = 0; t < NT; ++t)
        #pragma unroll
        for (int r = 0; r < 4; ++r) acc[t][r] = 0.0f;

    int nb[7], m7[7];
    #pragma unroll
    for (int p = 0; p < 6; ++p) {
        int n = (2 * p + (lane >> 4)) * 8 + (lane & 7);
        nb[p] = n * 1024; m7[p] = n & 7;
    }
    { int n = 96 + (lane & 7); nb[6] = n * 1024; m7[6] = n & 7; }
    const int khB = (lane >> 3) & 1;

    uint32_t fbuf[2][24];                    // double-buffered B fragments (tiles 0-11)
    uint32_t fb12[2][2];                     // tile 12 (x2)
    auto loadB24 = [&](int ks, int b) {
        const int cb = ks * 2 + khB;
        #pragma unroll
        for (int p = 0; p < 6; ++p) {
            uint32_t addr = sb + (uint32_t)(nb[p] + ((cb ^ m7[p]) << 4));
            asm volatile("ldmatrix.sync.aligned.m8n8.x4.shared.b16 "
                         "{%0,%1,%2,%3}, [%4];"
                         : "=r"(fbuf[b][4*p]), "=r"(fbuf[b][4*p+1]),
                           "=r"(fbuf[b][4*p+2]), "=r"(fbuf[b][4*p+3]) : "r"(addr));
        }
    };
    auto loadB12 = [&](int ks, int b) {
        const int cb = ks * 2 + khB;
        uint32_t addr = sb + (uint32_t)(nb[6] + ((cb ^ m7[6]) << 4));
        asm volatile("ldmatrix.sync.aligned.m8n8.x2.shared.b16 "
                     "{%0,%1}, [%2];"
                     : "=r"(fb12[b][0]), "=r"(fb12[b][1]) : "r"(addr));
    };

    const int arow0 = (warp * 16 + gid) * AROW + ctg * 8;

    // first chunk + full B tile must be resident before first loads
    asm volatile("cp.async.wait_group 1;" ::: "memory");
    __syncthreads();
    stageA(2);
    loadB24(0, 0);
    loadB12(0, 0);

    #pragma unroll 1
    for (int c = 0; c < 8; ++c) {
        const char* Ab = smem + SM_AR + (c % 3) * ACH;

        #pragma unroll
        for (int kl = 0; kl < 4; ++kl) {
            const int ks = c * 4 + kl;
            const int cur = ks & 1;
            // A fragment from ring (LDS.64 x4 + cvt)
            const char* a0p = Ab + arow0 + kl * 64;
            const char* a1p = a0p + 8 * AROW;
            float2 g0 = *(const float2*)(a0p);
            float2 g2 = *(const float2*)(a0p + 32);
            float2 g1 = *(const float2*)(a1p);
            float2 g3 = *(const float2*)(a1p + 32);
            if (ks < 31) { loadB24(ks + 1, cur ^ 1); loadB12(ks + 1, cur ^ 1); }
            uint32_t a0 = bf2(g0.x, g0.y), a1 = bf2(g1.x, g1.y);
            uint32_t a2 = bf2(g2.x, g2.y), a3 = bf2(g3.x, g3.y);
            #pragma unroll
            for (int p = 0; p < 6; ++p) {
                mma16816(acc[2*p],   a0, a1, a2, a3, fbuf[cur][4*p],   fbuf[cur][4*p+1]);
                mma16816(acc[2*p+1], a0, a1, a2, a3, fbuf[cur][4*p+2], fbuf[cur][4*p+3]);
            }
            mma16816(acc[12], a0, a1, a2, a3, fb12[cur][0], fb12[cur][1]);
        }

        // chunk boundary: next chunk must be resident; restage the freed buf
        if (c < 7) {
            if (c < 6) asm volatile("cp.async.wait_group 1;" ::: "memory");
            else       asm volatile("cp.async.wait_group 0;" ::: "memory");
            __syncthreads();
            if (c + 3 < 8) stageA(c + 3);
        }
    }

    // ---- epilogue: softplus over all 128x104 noise scores
    #pragma unroll
    for (int nt = 0; nt < NT; ++nt) {
        float c0 = sC[nt * 8 + ctg * 2];
        float c1 = sC[nt * 8 + ctg * 2 + 1];
        myLoss += softplus_fast(acc[nt][0] + c0);
        myLoss += softplus_fast(acc[nt][1] + c1);
        myLoss += softplus_fast(acc[nt][2] + c0);
        myLoss += softplus_fast(acc[nt][3] + c1);
    }

    // ---- block reduce
    #pragma unroll
    for (int d = 16; d >= 1; d >>= 1)
        myLoss += __shfl_xor_sync(0xffffffffu, myLoss, d);
    if (lane == 0) sRed[warp] = myLoss;
    __syncthreads();

    // ---- cross-block: last block reduces (single kernel)
    if (tid == 0) {
        float s = 0.f;
        #pragma unroll
        for (int w = 0; w < 8; ++w) s += sRed[w];
        g_partials[blockIdx.x] = s;
        __threadfence();
        unsigned n = atomicAdd(&g_counter, 1u);
        sFlag[0] = (n == GRID1 - 1) ? 1 : 0;
    }
    __syncthreads();
    if (sFlag[0]) {
        float v = (tid < GRID1) ? g_partials[tid] : 0.f;
        #pragma unroll
        for (int d = 16; d >= 1; d >>= 1)
            v += __shfl_xor_sync(0xffffffffu, v, d);
        if (lane == 0) sRed[warp] = v;
        __syncthreads();
        if (tid == 0) {
            float s = 0.f;
            #pragma unroll
            for (int w = 0; w < 8; ++w) s += sRed[w];
            out[0] = s * (1.0f / (float)NTOK);
            g_counter = 0u;                  // reset for next graph replay
        }
    }
}

extern "C" void kernel_launch(void* const* d_in, const int* in_sizes, int n_in,
                              void* d_out, int out_size) {
    (void)in_sizes; (void)n_in; (void)out_size;
    const float* inp       = (const float*)d_in[0];
    const float* emb       = (const float*)d_in[1];
    const float* bias      = (const float*)d_in[2];
    const float* logn      = (const float*)d_in[3];
    const int*   target    = (const int*)d_in[4];
    const int*   noise_idx = (const int*)d_in[5];

    float csub = logf(50257.0f) + logf(100.0f);   // NORM_TERM + LOG_NR

    cudaFuncSetAttribute(nce_hmma, cudaFuncAttributeMaxDynamicSharedMemorySize, SM_TOTAL);
    nce_hmma<<<GRID1, TPB, SM_TOTAL>>>(inp, emb, bias, logn, target, noise_idx,
                                       csub, (float*)d_out);
}

// round 14
// speedup vs baseline: 1.2711x; 1.1840x over previous
#include <cuda_runtime.h>
#include <cuda_bf16.h>
#include <math.h>
#include <stdint.h>

// NCE loss: scores(16384x104) = inp(16384x512) @ noise_emb^T via HMMA bf16.
// Grid=128 CTAs x 256 thr, 128 tokens/CTA, 1 CTA/SM.
// A: WARP-PRIVATE cp.async rings (5 slots x 2-kstep chunks). Each warp stages
// its own 16 rows and waits on its own group counter -> the GEMM main loop
// has NO CTA barriers and NO global loads. B: smem bf16 (XOR-swizzled),
// single-buffered fragments (R4-champion core, regs ~140).
// Ring prologue issued first so A lands during B-stage + target phases.

#define E      512
#define NRR    100
#define NP     104          // 13 * 8
#define NT     13
#define TPB    256
#define GRID1  128
#define NTOK   16384

#define AROW   160          // 32 f32 (128B data) + 32B pad (conflict-free LDS.64)
#define ACH    2560         // 16 rows * 160
#define RING   5
#define WRING  12800        // RING * ACH per warp
#define SM_B     0          // 104 * 1024
#define SM_SC    106496     // 104 floats
#define SM_NID   106912     // 104 ints
#define SM_RED   107328     // 8 floats
#define SM_FLAG  107392
#define SM_AR    107424     // 8 * 12800 = 102400
#define SM_TOTAL 209824

__device__ float        g_partials[GRID1];
__device__ unsigned int g_counter;

struct __align__(16) u64x2 { unsigned long long x, y; };

__device__ __forceinline__ unsigned long long fma2(unsigned long long a,
                                                   unsigned long long b,
                                                   unsigned long long c) {
    unsigned long long d;
    asm("fma.rn.f32x2 %0, %1, %2, %3;" : "=l"(d) : "l"(a), "l"(b), "l"(c));
    return d;
}
__device__ __forceinline__ float pairsum(unsigned long long u) {
    float lo, hi;
    asm("mov.b64 {%0, %1}, %2;" : "=f"(lo), "=f"(hi) : "l"(u));
    return lo + hi;
}
__device__ __forceinline__ float softplus_fast(float x) {
    return fmaxf(x, 0.0f) + __logf(1.0f + __expf(-fabsf(x)));
}
__device__ __forceinline__ uint32_t smem_u32(const void* p) {
    uint32_t a;
    asm("{ .reg .u64 t; cvta.to.shared.u64 t, %1; cvt.u32.u64 %0, t; }"
        : "=r"(a) : "l"(p));
    return a;
}
__device__ __forceinline__ uint32_t bf2(float lo, float hi) {
    uint32_t r;
    asm("cvt.rn.bf16x2.f32 %0, %1, %2;" : "=r"(r) : "f"(hi), "f"(lo));
    return r;
}
__device__ __forceinline__ void mma16816(float* d,
        uint32_t a0, uint32_t a1, uint32_t a2, uint32_t a3,
        uint32_t b0, uint32_t b1) {
    asm volatile("mma.sync.aligned.m16n8k16.row.col.f32.bf16.bf16.f32 "
        "{%0,%1,%2,%3}, {%4,%5,%6,%7}, {%8,%9}, {%0,%1,%2,%3};"
        : "+f"(d[0]), "+f"(d[1]), "+f"(d[2]), "+f"(d[3])
        : "r"(a0), "r"(a1), "r"(a2), "r"(a3), "r"(b0), "r"(b1));
}

__global__ void __launch_bounds__(TPB, 1)
nce_hmma(const float* __restrict__ inp,
         const float* __restrict__ emb,
         const float* __restrict__ bias,
         const float* __restrict__ logn,
         const int*   __restrict__ target,
         const int*   __restrict__ noise_idx,
         float csub, float* __restrict__ out)
{
    extern __shared__ char smem[];
    const uint32_t sb = smem_u32(smem);
    const int tid = threadIdx.x, warp = tid >> 5, lane = tid & 31;
    const int gid = lane >> 2, ctg = lane & 3;
    float* sC    = (float*)(smem + SM_SC);
    int*   sNid  = (int*)(smem + SM_NID);
    float* sRed  = (float*)(smem + SM_RED);
    int*   sFlag = (int*)(smem + SM_FLAG);
    const int tokBase = blockIdx.x * 128;

    // ---- warp-private A ring: chunk c = this warp's 16 rows x 32 f32
    const uint32_t wbase = sb + (uint32_t)(SM_AR + warp * WRING);
    const float* wsrc = inp + (size_t)(tokBase + warp * 16) * E;
    auto stageA = [&](int c) {
        const uint32_t dbase = wbase + (uint32_t)((c % RING) * ACH);
        const float* src0 = wsrc + c * 32;
        #pragma unroll
        for (int i = 0; i < 4; ++i) {
            int u = lane + i * 32;           // 128 16B-units per chunk
            int row = u >> 3, col = u & 7;
            const char* src = (const char*)(src0 + (size_t)row * E) + col * 16;
            uint32_t sa = dbase + (uint32_t)(row * AROW + col * 16);
            asm volatile("cp.async.cg.shared.global [%0], [%1], 16;"
                         :: "r"(sa), "l"(src));
        }
        asm volatile("cp.async.commit_group;");
    };
    // prologue: 4 chunks in flight per warp (~10KB) land during B/target phases
    stageA(0); stageA(1); stageA(2); stageA(3);

    // ---- column ids + constants
    if (tid < NP) {
        int nid = (tid < NRR) ? noise_idx[tid] : 0;
        sNid[tid] = nid;
        sC[tid] = (tid < NRR) ? (bias[nid] - logn[nid] - csub) : -INFINITY;
    }
    __syncthreads();

    // ---- stage B: 104 x 512 bf16, 16B chunks XOR-swizzled
    #pragma unroll 4
    for (int i = 0; i < 26; ++i) {
        int idx = tid + i * TPB;
        int n = idx >> 6, c = idx & 63;
        uint4 pk = make_uint4(0u, 0u, 0u, 0u);
        if (n < NRR) {
            const float4* r = (const float4*)(emb + (size_t)sNid[n] * E) + (c << 1);
            float4 v0 = r[0], v1 = r[1];
            pk.x = bf2(v0.x, v0.y); pk.y = bf2(v0.z, v0.w);
            pk.z = bf2(v1.x, v1.y); pk.w = bf2(v1.z, v1.w);
        }
        *(uint4*)(smem + SM_B + n * 1024 + ((c ^ (n & 7)) << 4)) = pk;
    }
    __syncthreads();

    float myLoss = 0.0f;

    // ---- target dots: 16 tokens/warp, 4 in flight (fp32 exact)
    #pragma unroll 1
    for (int i = 0; i < 16; i += 4) {
        int tb = tokBase + warp * 16 + i;
        int tg[4];
        #pragma unroll
        for (int j = 0; j < 4; ++j) tg[j] = target[tb + j];
        unsigned long long A[4] = {0ull, 0ull, 0ull, 0ull};
        #pragma unroll
        for (int q = 0; q < 4; ++q) {
            u64x2 av[4], bv[4];
            #pragma unroll
            for (int j = 0; j < 4; ++j) {
                av[j] = ((const u64x2*)(inp + (size_t)(tb + j) * E))[lane + q * 32];
                bv[j] = ((const u64x2*)(emb + (size_t)tg[j] * E))[lane + q * 32];
            }
            #pragma unroll
            for (int j = 0; j < 4; ++j) {
                A[j] = fma2(av[j].x, bv[j].x, A[j]);
                A[j] = fma2(av[j].y, bv[j].y, A[j]);
            }
        }
        #pragma unroll
        for (int j = 0; j < 4; ++j) {
            float s = pairsum(A[j]);
            #pragma unroll
            for (int d = 16; d >= 1; d >>= 1)
                s += __shfl_xor_sync(0xffffffffu, s, d);
            if (lane == 0)
                myLoss += softplus_fast(-(s + bias[tg[j]] - logn[tg[j]] - csub));
        }
    }

    // ---- GEMM: 16 rows x 13 tiles, K=512 = 16 warp-private chunks x 2 ksteps
    float acc[NT][4];
    #pragma unroll
    for (int t = 0; t < NT; ++t)
        #pragma unroll
        for (int r = 0; r < 4; ++r) acc[t][r] = 0.0f;

    int nb[7], m7[7];
    #pragma unroll
    for (int p = 0; p < 6; ++p) {
        int n = (2 * p + (lane >> 4)) * 8 + (lane & 7);
        nb[p] = n * 1024; m7[p] = n & 7;
    }
    { int n = 96 + (lane & 7); nb[6] = n * 1024; m7[6] = n & 7; }
    const int khB = (lane >> 3) & 1;

    const int aoff0 = gid * AROW + ctg * 8;          // row gid, elems ctg*2..+1
    const int aoff1 = (gid + 8) * AROW + ctg * 8;    // row gid+8

    #pragma unroll 1
    for (int c = 0; c < 16; ++c) {
        // wait for this warp's chunk c (per-warp, NO CTA barrier)
        if (c < 13)      asm volatile("cp.async.wait_group 3;" ::: "memory");
        else if (c == 13) asm volatile("cp.async.wait_group 2;" ::: "memory");
        else if (c == 14) asm volatile("cp.async.wait_group 1;" ::: "memory");
        else              asm volatile("cp.async.wait_group 0;" ::: "memory");
        __syncwarp();
        if (c + 4 < 16) stageA(c + 4);   // slot (c+4)%5 == (c-1)%5, already consumed

        const char* Ab = smem + (wbase - sb) + (c % RING) * ACH;

        #pragma unroll
        for (int kl = 0; kl < 2; ++kl) {
            const int ks = c * 2 + kl;
            const char* a0p = Ab + aoff0 + kl * 64;
            const char* a1p = Ab + aoff1 + kl * 64;
            float2 g0 = *(const float2*)(a0p);
            float2 g2 = *(const float2*)(a0p + 32);
            float2 g1 = *(const float2*)(a1p);
            float2 g3 = *(const float2*)(a1p + 32);
            uint32_t a0 = bf2(g0.x, g0.y), a1 = bf2(g1.x, g1.y);
            uint32_t a2 = bf2(g2.x, g2.y), a3 = bf2(g3.x, g3.y);

            const int cb = ks * 2 + khB;
            #pragma unroll
            for (int p = 0; p < 6; ++p) {
                uint32_t b0, b1, b2, b3;
                uint32_t addr = sb + (uint32_t)(nb[p] + ((cb ^ m7[p]) << 4));
                asm volatile("ldmatrix.sync.aligned.m8n8.x4.shared.b16 "
                             "{%0,%1,%2,%3}, [%4];"
                             : "=r"(b0), "=r"(b1), "=r"(b2), "=r"(b3) : "r"(addr));
                mma16816(acc[2 * p],     a0, a1, a2, a3, b0, b1);
                mma16816(acc[2 * p + 1], a0, a1, a2, a3, b2, b3);
            }
            {
                uint32_t b0, b1;
                uint32_t addr = sb + (uint32_t)(nb[6] + ((cb ^ m7[6]) << 4));
                asm volatile("ldmatrix.sync.aligned.m8n8.x2.shared.b16 "
                             "{%0,%1}, [%2];"
                             : "=r"(b0), "=r"(b1) : "r"(addr));
                mma16816(acc[12], a0, a1, a2, a3, b0, b1);
            }
        }
    }

    // ---- epilogue: softplus over all 128x104 noise scores
    #pragma unroll
    for (int nt = 0; nt < NT; ++nt) {
        float c0 = sC[nt * 8 + ctg * 2];
        float c1 = sC[nt * 8 + ctg * 2 + 1];
        myLoss += softplus_fast(acc[nt][0] + c0);
        myLoss += softplus_fast(acc[nt][1] + c1);
        myLoss += softplus_fast(acc[nt][2] + c0);
        myLoss += softplus_fast(acc[nt][3] + c1);
    }

    // ---- block reduce
    #pragma unroll
    for (int d = 16; d >= 1; d >>= 1)
        myLoss += __shfl_xor_sync(0xffffffffu, myLoss, d);
    if (lane == 0) sRed[warp] = myLoss;
    __syncthreads();

    // ---- cross-block: last block reduces (single kernel)
    if (tid == 0) {
        float s = 0.f;
        #pragma unroll
        for (int w = 0; w < 8; ++w) s += sRed[w];
        g_partials[blockIdx.x] = s;
        __threadfence();
        unsigned n = atomicAdd(&g_counter, 1u);
        sFlag[0] = (n == GRID1 - 1) ? 1 : 0;
    }
    __syncthreads();
    if (sFlag[0]) {
        float v = (tid < GRID1) ? g_partials[tid] : 0.f;
        #pragma unroll
        for (int d = 16; d >= 1; d >>= 1)
            v += __shfl_xor_sync(0xffffffffu, v, d);
        if (lane == 0) sRed[warp] = v;
        __syncthreads();
        if (tid == 0) {
            float s = 0.f;
            #pragma unroll
            for (int w = 0; w < 8; ++w) s += sRed[w];
            out[0] = s * (1.0f / (float)NTOK);
            g_counter = 0u;                  // reset for next graph replay
        }
    }
}

extern "C" void kernel_launch(void* const* d_in, const int* in_sizes, int n_in,
                              void* d_out, int out_size) {
    (void)in_sizes; (void)n_in; (void)out_size;
    const float* inp       = (const float*)d_in[0];
    const float* emb       = (const float*)d_in[1];
    const float* bias      = (const float*)d_in[2];
    const float* logn      = (const float*)d_in[3];
    const int*   target    = (const int*)d_in[4];
    const int*   noise_idx = (const int*)d_in[5];

    float csub = logf(50257.0f) + logf(100.0f);   // NORM_TERM + LOG_NR

    cudaFuncSetAttribute(nce_hmma, cudaFuncAttributeMaxDynamicSharedMemorySize, SM_TOTAL);
    nce_hmma<<<GRID1, TPB, SM_TOTAL>>>(inp, emb, bias, logn, target, noise_idx,
                                       csub, (float*)d_out);
}